// round 1
// baseline (speedup 1.0000x reference)
#include <cuda_runtime.h>

// SimpleSSM: h_t = A*h_{t-1} + B*x_t ; y_t = C*h_t + D*x_t ; out = LayerNorm_dm(y)
// x: [8, 4096, 1024] f32. Diagonal recurrence -> chunked parallel scan + fused LN.

#define BSZ       8
#define SEQ_T     4096
#define DM        1024
#define DM4       (DM / 4)        // 256 float4 lanes per row
#define N_CHUNK   64              // chunks along T
#define L_CHUNK   (SEQ_T / N_CHUNK) // 64 timesteps per chunk
#define LN_EPS    1e-5f
#define NTHREADS  256             // = DM4, one float4 column per thread

// Scratch: per-(b, chunk, dm) carry. Phase1 writes local sums, phase2 rewrites
// in-place to h_in (state at chunk start). 8*64*1024 floats = 2 MB.
__device__ float g_carry[BSZ * N_CHUNK * DM];

// ---------------------------------------------------------------------------
// Phase 1: chunk-local scan  s_c = sum_{i=0}^{L-1} A^{L-1-i} * B * x_{cL+i}
// computed with the same forward recurrence as the reference (s = A*s + B*x).
// ---------------------------------------------------------------------------
__global__ __launch_bounds__(NTHREADS, 8)
void ssm_phase1(const float* __restrict__ x,
                const float4* __restrict__ A4,
                const float4* __restrict__ B4) {
    const int blk = blockIdx.x;              // b * N_CHUNK + c
    const int b   = blk / N_CHUNK;
    const int c   = blk % N_CHUNK;
    const int tid = threadIdx.x;             // 0..255 -> dm = 4*tid..4*tid+3

    const float4 a  = A4[tid];
    const float4 bb = B4[tid];

    const float4* xp = reinterpret_cast<const float4*>(x)
                     + (size_t)(b * SEQ_T + c * L_CHUNK) * DM4 + tid;

    float4 s = make_float4(0.f, 0.f, 0.f, 0.f);
    #pragma unroll 8
    for (int t = 0; t < L_CHUNK; t++) {
        float4 xv = xp[(size_t)t * DM4];
        s.x = fmaf(a.x, s.x, bb.x * xv.x);
        s.y = fmaf(a.y, s.y, bb.y * xv.y);
        s.z = fmaf(a.z, s.z, bb.z * xv.z);
        s.w = fmaf(a.w, s.w, bb.w * xv.w);
    }
    reinterpret_cast<float4*>(g_carry)[(size_t)(b * N_CHUNK + c) * DM4 + tid] = s;
}

// ---------------------------------------------------------------------------
// Phase 2: scan the N_CHUNK carries per (b, dm):
//   H_{-1} = 0 ; h_in[c] = H_{c-1} ; H_c = A^L * H_{c-1} + s_c
// Rewrites g_carry[b][c][:] from s_c to h_in[c].
// ---------------------------------------------------------------------------
__global__ __launch_bounds__(NTHREADS, 8)
void ssm_phase2(const float4* __restrict__ A4) {
    const int b   = blockIdx.x;              // 0..7
    const int tid = threadIdx.x;             // 0..255

    float4 aL = A4[tid];
    #pragma unroll
    for (int i = 0; i < 6; i++) {            // A^64 via repeated squaring
        aL.x *= aL.x; aL.y *= aL.y; aL.z *= aL.z; aL.w *= aL.w;
    }

    float4* carry = reinterpret_cast<float4*>(g_carry)
                  + (size_t)b * N_CHUNK * DM4 + tid;

    float4 h = make_float4(0.f, 0.f, 0.f, 0.f);
    #pragma unroll 4
    for (int c = 0; c < N_CHUNK; c++) {
        float4 s = carry[(size_t)c * DM4];
        carry[(size_t)c * DM4] = h;          // h_in for chunk c
        h.x = fmaf(aL.x, h.x, s.x);
        h.y = fmaf(aL.y, h.y, s.y);
        h.z = fmaf(aL.z, h.z, s.z);
        h.w = fmaf(aL.w, h.w, s.w);
    }
}

// ---------------------------------------------------------------------------
// Phase 3: one block per (b, chunk). Each thread owns 4 channels; per timestep
// run the exact recurrence, block-reduce (sum, sumsq) over the 1024 channels,
// apply LN, write out. x loads for t+1 are prefetched past the barriers.
// ---------------------------------------------------------------------------
__global__ __launch_bounds__(NTHREADS, 4)
void ssm_phase3(const float* __restrict__ x,
                const float4* __restrict__ A4,
                const float4* __restrict__ B4,
                const float4* __restrict__ C4,
                const float4* __restrict__ D4,
                const float4* __restrict__ G4,
                const float4* __restrict__ E4,
                float* __restrict__ out) {
    __shared__ float red_sum[8];
    __shared__ float red_sq[8];
    __shared__ float stats[2];               // mean, rstd

    const int blk  = blockIdx.x;             // b * N_CHUNK + c
    const int b    = blk / N_CHUNK;
    const int c    = blk % N_CHUNK;
    const int tid  = threadIdx.x;
    const int lane = tid & 31;
    const int wid  = tid >> 5;

    const float4 a  = A4[tid];
    const float4 bb = B4[tid];
    const float4 cc = C4[tid];
    const float4 dd = D4[tid];
    const float4 g  = G4[tid];
    const float4 be = E4[tid];

    float4 h = reinterpret_cast<const float4*>(g_carry)
                   [(size_t)(b * N_CHUNK + c) * DM4 + tid];

    const size_t row0 = (size_t)(b * SEQ_T + c * L_CHUNK) * DM4 + tid;
    const float4* xp = reinterpret_cast<const float4*>(x) + row0;
    float4*       op = reinterpret_cast<float4*>(out)     + row0;

    float4 xv = xp[0];
    #pragma unroll 2
    for (int t = 0; t < L_CHUNK; t++) {
        // Prefetch next row (clamped) before the reduction barriers.
        const int tn = (t + 1 < L_CHUNK) ? (t + 1) : t;
        float4 xn = xp[(size_t)tn * DM4];

        h.x = fmaf(a.x, h.x, bb.x * xv.x);
        h.y = fmaf(a.y, h.y, bb.y * xv.y);
        h.z = fmaf(a.z, h.z, bb.z * xv.z);
        h.w = fmaf(a.w, h.w, bb.w * xv.w);

        float4 y;
        y.x = fmaf(cc.x, h.x, dd.x * xv.x);
        y.y = fmaf(cc.y, h.y, dd.y * xv.y);
        y.z = fmaf(cc.z, h.z, dd.z * xv.z);
        y.w = fmaf(cc.w, h.w, dd.w * xv.w);

        float s1 = y.x + y.y + y.z + y.w;
        float s2 = fmaf(y.x, y.x, fmaf(y.y, y.y, fmaf(y.z, y.z, y.w * y.w)));

        #pragma unroll
        for (int off = 16; off > 0; off >>= 1) {
            s1 += __shfl_xor_sync(0xFFFFFFFFu, s1, off);
            s2 += __shfl_xor_sync(0xFFFFFFFFu, s2, off);
        }
        if (lane == 0) { red_sum[wid] = s1; red_sq[wid] = s2; }
        __syncthreads();
        if (tid < 32) {
            float r1 = (tid < 8) ? red_sum[tid] : 0.f;
            float r2 = (tid < 8) ? red_sq[tid]  : 0.f;
            #pragma unroll
            for (int off = 4; off > 0; off >>= 1) {
                r1 += __shfl_xor_sync(0xFFFFFFFFu, r1, off);
                r2 += __shfl_xor_sync(0xFFFFFFFFu, r2, off);
            }
            if (tid == 0) {
                float mu  = r1 * (1.f / DM);
                float var = fmaf(r2, 1.f / DM, -mu * mu);
                if (var < 0.f) var = 0.f;
                stats[0] = mu;
                stats[1] = rsqrtf(var + LN_EPS);
            }
        }
        __syncthreads();
        const float mu = stats[0];
        const float rs = stats[1];

        float4 o;
        o.x = fmaf((y.x - mu) * rs, g.x, be.x);
        o.y = fmaf((y.y - mu) * rs, g.y, be.y);
        o.z = fmaf((y.z - mu) * rs, g.z, be.z);
        o.w = fmaf((y.w - mu) * rs, g.w, be.w);
        op[(size_t)t * DM4] = o;

        xv = xn;
        __syncthreads();   // protect red_sum/stats reuse next iteration
    }
}

// ---------------------------------------------------------------------------
extern "C" void kernel_launch(void* const* d_in, const int* in_sizes, int n_in,
                              void* d_out, int out_size) {
    const float*  x  = (const float*)d_in[0];
    const float4* A4 = (const float4*)d_in[1];
    const float4* B4 = (const float4*)d_in[2];
    const float4* C4 = (const float4*)d_in[3];
    const float4* D4 = (const float4*)d_in[4];
    const float4* G4 = (const float4*)d_in[5];
    const float4* E4 = (const float4*)d_in[6];
    float* out = (float*)d_out;

    ssm_phase1<<<BSZ * N_CHUNK, NTHREADS>>>(x, A4, B4);
    ssm_phase2<<<BSZ, NTHREADS>>>(A4);
    ssm_phase3<<<BSZ * N_CHUNK, NTHREADS>>>(x, A4, B4, C4, D4, G4, E4, out);
}